// round 16
// baseline (speedup 1.0000x reference)
#include <cuda_runtime.h>
#include <cuda_fp16.h>
#include <stdint.h>

#define N_NODES 50000
#define N_EDGES 800000
#define NB      208            // scan blocks: 208*256 = 53248 >= N_NODES

// ---------------- scratch (allocation-free: __device__ globals) ----------------
__device__ __align__(16) float  g_dinv[N_NODES];
__device__ __align__(16) __half g_h16[N_NODES * 128]; // GEMM out (dinv-prescaled), fp16
__device__ __align__(16) __half g_o16[N_NODES * 128]; // layer output (fp16, next GEMM A)
__device__ __align__(16) __half g_w1t[128 * 128];     // W1^T fp16 (n-major rows of 128)
__device__ __align__(16) __half g_w2t[128 * 128];     // W2^T fp16
__device__ __align__(16) __half g_w3t[64 * 128];      // W3^T fp16
__device__ __align__(16) int g_adj[N_EDGES];
__device__ int g_off[N_NODES + 1];
__device__ int g_cur[N_NODES];
__device__ int g_degi[N_NODES];
__device__ int g_bsum[NB];
__device__ int g_is64;

// ---------------- detect dtype + zero degrees (one launch) ----------------
__global__ void detect_zero_kernel(const int* __restrict__ ei_raw) {
    int i = blockIdx.x * 256 + threadIdx.x;
    if (i < N_NODES) g_degi[i] = 0;
    if (blockIdx.x == 0) {
        __shared__ int any;
        if (threadIdx.x == 0) any = 0;
        __syncthreads();
        int nz = 0;
        for (int j = threadIdx.x; j < 1024; j += 256)
            nz |= ei_raw[2 * j + 1];
        if (nz) atomicOr(&any, 1);
        __syncthreads();
        if (threadIdx.x == 0) g_is64 = (any == 0);
    }
}

__global__ void count_kernel(const int* __restrict__ ei_raw) {
    int i = blockIdx.x * blockDim.x + threadIdx.x;
    if (i >= N_EDGES) return;
    int c = g_is64 ? ei_raw[2 * (N_EDGES + i)] : ei_raw[N_EDGES + i];
    atomicAdd(&g_degi[c], 1);
}

__global__ void dinv_kernel() {
    int i = blockIdx.x * 256 + threadIdx.x;
    if (i < N_NODES) g_dinv[i] = rsqrtf((float)(1 + g_degi[i]));
}

// ---------------- weight transpose to fp16 n-major: out[n][k] = W[k][n] -------
template <int WID, int N>
__global__ void wt_kernel(const float* __restrict__ W) {
    __half* outp = (WID == 1) ? g_w1t : (WID == 2) ? g_w2t : g_w3t;
    int idx = blockIdx.x * 256 + threadIdx.x;
    if (idx >= 128 * N) return;
    int n = idx % N;
    int k = idx / N;
    outp[n * 128 + k] = __float2half(W[(size_t)k * N + n]);
}

// ---------------- post-join row scaling for layer 1: g_h16[r,:] *= dinv[r] ----
__global__ void scale_h_kernel() {
    int idx = blockIdx.x * 256 + threadIdx.x;   // over N_NODES*16 uint4
    if (idx >= N_NODES * 16) return;
    int row = idx >> 4;
    float w = g_dinv[row];
    uint4 u = ((const uint4*)g_h16)[idx];
    __half2* h = (__half2*)&u;
#pragma unroll
    for (int j = 0; j < 4; j++) {
        float2 f = __half22float2(h[j]);
        h[j] = __floats2half2_rn(f.x * w, f.y * w);
    }
    ((uint4*)g_h16)[idx] = u;
}

// ---------------- scan phase A: per-block degree sums ----------------
__global__ __launch_bounds__(256) void scanA_kernel() {
    __shared__ int sh[256];
    int i = blockIdx.x * 256 + threadIdx.x;
    int v = (i < N_NODES) ? g_degi[i] : 0;
    sh[threadIdx.x] = v;
    __syncthreads();
    for (int o = 128; o > 0; o >>= 1) {
        if (threadIdx.x < o) sh[threadIdx.x] += sh[threadIdx.x + o];
        __syncthreads();
    }
    if (threadIdx.x == 0) g_bsum[blockIdx.x] = sh[0];
}

// ---------------- scan phase B+C merged: offsets + cursors ----------------
__global__ __launch_bounds__(256) void scanBC_kernel() {
    __shared__ int pre[256];
    __shared__ int sh[256];
    int t = threadIdx.x;

    pre[t] = (t < NB && t < blockIdx.x) ? g_bsum[t] : 0;
    __syncthreads();
    for (int o = 128; o > 0; o >>= 1) {
        if (t < o) pre[t] += pre[t + o];
        __syncthreads();
    }
    int bpref = pre[0];

    int i = blockIdx.x * 256 + t;
    int d = (i < N_NODES) ? g_degi[i] : 0;
    sh[t] = d;
    __syncthreads();
    for (int o = 1; o < 256; o <<= 1) {
        int x = sh[t];
        int a = (t >= o) ? sh[t - o] : 0;
        __syncthreads();
        sh[t] = x + a;
        __syncthreads();
    }
    if (i < N_NODES) {
        int excl = sh[t] - d + bpref;
        g_off[i] = excl;
        g_cur[i] = excl;
    }
    if (i == 0) g_off[N_NODES] = N_EDGES;
}

__global__ void fill_kernel(const int* __restrict__ ei_raw) {
    int i = blockIdx.x * blockDim.x + threadIdx.x;
    if (i >= N_EDGES) return;
    int r, c;
    if (g_is64) {
        r = ei_raw[2 * i];
        c = ei_raw[2 * (N_EDGES + i)];
    } else {
        r = ei_raw[i];
        c = ei_raw[N_EDGES + i];
    }
    int pos = atomicAdd(&g_cur[c], 1);
    g_adj[pos] = r;
}

// ---------------- fp16 GEMM, full-K single-stage ----------
// DINV=1: epilogue scales rows by g_dinv; DINV=0: raw store (layer-1 early start).
#define LDK 136   // padded row length in halfs

template <int BN, int SRC, int WID, int DINV>
__global__ __launch_bounds__(256, 2) void gemm_tc_kernel(
    const float* __restrict__ Aext)
{
    constexpr int WN = BN / 4;
    constexpr int NF = WN / 8;

    extern __shared__ __half sm[];
    __half* Ah = sm;                    // [128][LDK]
    __half* Bh = sm + 128 * LDK;        // [BN][LDK]

    const __half* Bt = (WID == 1) ? g_w1t : (WID == 2) ? g_w2t : g_w3t;

    int tid  = threadIdx.x;
    int warp = tid >> 5;
    int lane = tid & 31;
    int gid  = lane >> 2;
    int tig  = lane & 3;
    int warp_m = warp >> 2;
    int warp_n = warp & 3;
    int rowBase = blockIdx.y * 128;

    // ---- stage A: 128 rows x 128 halfs ----
    if (SRC == 0) {
#pragma unroll
        for (int i = 0; i < 32; i++) {
            int idx = tid + i * 256;
            int m  = idx >> 6;
            int k2 = idx & 63;
            int gm = rowBase + m;
            float2 v = (gm < N_NODES)
                ? *(const float2*)&Aext[(size_t)gm * 128 + 2 * k2]
                : make_float2(0.0f, 0.0f);
            *(__half2*)&Ah[m * LDK + 2 * k2] = __float22half2_rn(v);
        }
    } else {
#pragma unroll
        for (int i = 0; i < 8; i++) {
            int idx = tid + i * 256;
            int m = idx >> 4;
            int j = idx & 15;
            int gm = rowBase + m;
            uint4 v = (gm < N_NODES)
                ? *(const uint4*)&g_o16[(size_t)gm * 128 + 8 * j]
                : make_uint4(0, 0, 0, 0);
            *(uint4*)&Ah[m * LDK + 8 * j] = v;
        }
    }
    // ---- stage B from pre-transposed fp16 ----
#pragma unroll
    for (int i = 0; i < (BN * 16) / 256; i++) {
        int idx = tid + i * 256;
        int n = idx >> 4;
        int j = idx & 15;
        uint4 v = *(const uint4*)&Bt[n * 128 + 8 * j];
        *(uint4*)&Bh[n * LDK + 8 * j] = v;
    }
    __syncthreads();

    float acc[4][NF][4];
#pragma unroll
    for (int mf = 0; mf < 4; mf++)
#pragma unroll
        for (int nf = 0; nf < NF; nf++)
#pragma unroll
            for (int q = 0; q < 4; q++) acc[mf][nf][q] = 0.0f;

#pragma unroll
    for (int ks = 0; ks < 8; ks++) {
        int k0 = ks * 16;
        unsigned a[4][4];
#pragma unroll
        for (int mf = 0; mf < 4; mf++) {
            int rb = warp_m * 64 + mf * 16;
            a[mf][0] = *(const unsigned*)&Ah[(rb + gid) * LDK + k0 + 2 * tig];
            a[mf][1] = *(const unsigned*)&Ah[(rb + gid + 8) * LDK + k0 + 2 * tig];
            a[mf][2] = *(const unsigned*)&Ah[(rb + gid) * LDK + k0 + 2 * tig + 8];
            a[mf][3] = *(const unsigned*)&Ah[(rb + gid + 8) * LDK + k0 + 2 * tig + 8];
        }
#pragma unroll
        for (int nf = 0; nf < NF; nf++) {
            int nb = warp_n * WN + nf * 8;
            unsigned b0 = *(const unsigned*)&Bh[(nb + gid) * LDK + k0 + 2 * tig];
            unsigned b1 = *(const unsigned*)&Bh[(nb + gid) * LDK + k0 + 2 * tig + 8];
#pragma unroll
            for (int mf = 0; mf < 4; mf++) {
                asm volatile(
                    "mma.sync.aligned.m16n8k16.row.col.f32.f16.f16.f32 "
                    "{%0,%1,%2,%3}, {%4,%5,%6,%7}, {%8,%9}, {%0,%1,%2,%3};"
                    : "+f"(acc[mf][nf][0]), "+f"(acc[mf][nf][1]),
                      "+f"(acc[mf][nf][2]), "+f"(acc[mf][nf][3])
                    : "r"(a[mf][0]), "r"(a[mf][1]),
                      "r"(a[mf][2]), "r"(a[mf][3]),
                      "r"(b0), "r"(b1));
            }
        }
    }

    // epilogue: optional dinv row scale, pack to half2, store to g_h16
#pragma unroll
    for (int mf = 0; mf < 4; mf++) {
        int r0 = rowBase + warp_m * 64 + mf * 16 + gid;
        int r1 = r0 + 8;
        bool p0 = (r0 < N_NODES);
        bool p1 = (r1 < N_NODES);
        float d0 = (DINV && p0) ? g_dinv[r0] : 1.0f;
        float d1 = (DINV && p1) ? g_dinv[r1] : 1.0f;
#pragma unroll
        for (int nf = 0; nf < NF; nf++) {
            int nc = warp_n * WN + nf * 8 + tig * 2;
            if (p0) {
                __half2 hv = __floats2half2_rn(acc[mf][nf][0] * d0, acc[mf][nf][1] * d0);
                *(__half2*)&g_h16[(size_t)r0 * BN + nc] = hv;
            }
            if (p1) {
                __half2 hv = __floats2half2_rn(acc[mf][nf][2] * d1, acc[mf][nf][3] * d1);
                *(__half2*)&g_h16[(size_t)r1 * BN + nc] = hv;
            }
        }
    }
}

// ---------------- CSR aggregate, DIM=128: 16 lanes/node, uint4 gathers, 8-deep MLP -------
#define ACC8(U)  do {                                                   \
    float2 _p;                                                          \
    _p = __half22float2(*(const __half2*)&(U).x); a0 += _p.x; a1 += _p.y; \
    _p = __half22float2(*(const __half2*)&(U).y); a2 += _p.x; a3 += _p.y; \
    _p = __half22float2(*(const __half2*)&(U).z); a4 += _p.x; a5 += _p.y; \
    _p = __half22float2(*(const __half2*)&(U).w); a6 += _p.x; a7 += _p.y; \
} while (0)

template <bool RELU>
__global__ __launch_bounds__(256) void agg128_kernel(const float* __restrict__ b)
{
    int gt = blockIdx.x * 256 + threadIdx.x;
    int c = gt >> 4;
    int sl = threadIdx.x & 15;
    if (c >= N_NODES) return;

    const uint4* hs = (const uint4*)g_h16;

    uint4 u = hs[(size_t)c * 16 + sl];
    float a0, a1, a2, a3, a4, a5, a6, a7;
    {
        float2 p;
        p = __half22float2(*(const __half2*)&u.x); a0 = p.x; a1 = p.y;
        p = __half22float2(*(const __half2*)&u.y); a2 = p.x; a3 = p.y;
        p = __half22float2(*(const __half2*)&u.z); a4 = p.x; a5 = p.y;
        p = __half22float2(*(const __half2*)&u.w); a6 = p.x; a7 = p.y;
    }

    int s = g_off[c], e = g_off[c + 1];
    int i = s;
    for (; i + 8 <= e; i += 8) {
        int r0 = g_adj[i],     r1 = g_adj[i + 1], r2 = g_adj[i + 2], r3 = g_adj[i + 3];
        int r4 = g_adj[i + 4], r5 = g_adj[i + 5], r6 = g_adj[i + 6], r7 = g_adj[i + 7];
        uint4 u0 = hs[(size_t)r0 * 16 + sl];
        uint4 u1 = hs[(size_t)r1 * 16 + sl];
        uint4 u2 = hs[(size_t)r2 * 16 + sl];
        uint4 u3 = hs[(size_t)r3 * 16 + sl];
        uint4 u4 = hs[(size_t)r4 * 16 + sl];
        uint4 u5 = hs[(size_t)r5 * 16 + sl];
        uint4 u6 = hs[(size_t)r6 * 16 + sl];
        uint4 u7 = hs[(size_t)r7 * 16 + sl];
        ACC8(u0); ACC8(u1); ACC8(u2); ACC8(u3);
        ACC8(u4); ACC8(u5); ACC8(u6); ACC8(u7);
    }
    for (; i < e; i++) {
        uint4 uv = hs[(size_t)g_adj[i] * 16 + sl];
        ACC8(uv);
    }

    float d = g_dinv[c];
    const float4* b4 = (const float4*)b;
    float4 bb0 = b4[sl * 2], bb1 = b4[sl * 2 + 1];
    float v0 = a0 * d + bb0.x, v1 = a1 * d + bb0.y;
    float v2 = a2 * d + bb0.z, v3 = a3 * d + bb0.w;
    float v4 = a4 * d + bb1.x, v5 = a5 * d + bb1.y;
    float v6 = a6 * d + bb1.z, v7 = a7 * d + bb1.w;
    if (RELU) {
        v0 = fmaxf(v0, 0.0f); v1 = fmaxf(v1, 0.0f);
        v2 = fmaxf(v2, 0.0f); v3 = fmaxf(v3, 0.0f);
        v4 = fmaxf(v4, 0.0f); v5 = fmaxf(v5, 0.0f);
        v6 = fmaxf(v6, 0.0f); v7 = fmaxf(v7, 0.0f);
    }
    __half2 h0 = __floats2half2_rn(v0, v1);
    __half2 h1 = __floats2half2_rn(v2, v3);
    __half2 h2 = __floats2half2_rn(v4, v5);
    __half2 h3 = __floats2half2_rn(v6, v7);
    uint4 w;
    w.x = *(unsigned*)&h0;  w.y = *(unsigned*)&h1;
    w.z = *(unsigned*)&h2;  w.w = *(unsigned*)&h3;
    ((uint4*)g_o16)[(size_t)c * 16 + sl] = w;
}

// DIM=64 final layer: 8 lanes per node, 8-deep MLP, writes d_out fp32.
__global__ __launch_bounds__(256) void agg64_kernel(float* __restrict__ out,
                                                    const float* __restrict__ b)
{
    int gt = blockIdx.x * 256 + threadIdx.x;
    int c = gt >> 3;
    int sl = threadIdx.x & 7;
    if (c >= N_NODES) return;

    const uint4* hs = (const uint4*)g_h16;

    uint4 u = hs[(size_t)c * 8 + sl];
    float a0, a1, a2, a3, a4, a5, a6, a7;
    {
        float2 p;
        p = __half22float2(*(const __half2*)&u.x); a0 = p.x; a1 = p.y;
        p = __half22float2(*(const __half2*)&u.y); a2 = p.x; a3 = p.y;
        p = __half22float2(*(const __half2*)&u.z); a4 = p.x; a5 = p.y;
        p = __half22float2(*(const __half2*)&u.w); a6 = p.x; a7 = p.y;
    }

    int s = g_off[c], e = g_off[c + 1];
    int i = s;
    for (; i + 8 <= e; i += 8) {
        int r0 = g_adj[i],     r1 = g_adj[i + 1], r2 = g_adj[i + 2], r3 = g_adj[i + 3];
        int r4 = g_adj[i + 4], r5 = g_adj[i + 5], r6 = g_adj[i + 6], r7 = g_adj[i + 7];
        uint4 u0 = hs[(size_t)r0 * 8 + sl];
        uint4 u1 = hs[(size_t)r1 * 8 + sl];
        uint4 u2 = hs[(size_t)r2 * 8 + sl];
        uint4 u3 = hs[(size_t)r3 * 8 + sl];
        uint4 u4 = hs[(size_t)r4 * 8 + sl];
        uint4 u5 = hs[(size_t)r5 * 8 + sl];
        uint4 u6 = hs[(size_t)r6 * 8 + sl];
        uint4 u7 = hs[(size_t)r7 * 8 + sl];
        ACC8(u0); ACC8(u1); ACC8(u2); ACC8(u3);
        ACC8(u4); ACC8(u5); ACC8(u6); ACC8(u7);
    }
    for (; i < e; i++) {
        uint4 uv = hs[(size_t)g_adj[i] * 8 + sl];
        ACC8(uv);
    }

    float d = g_dinv[c];
    const float4* b4 = (const float4*)b;
    float4 bb0 = b4[sl * 2], bb1 = b4[sl * 2 + 1];
    float4 r0v, r1v;
    r0v.x = a0 * d + bb0.x;  r0v.y = a1 * d + bb0.y;
    r0v.z = a2 * d + bb0.z;  r0v.w = a3 * d + bb0.w;
    r1v.x = a4 * d + bb1.x;  r1v.y = a5 * d + bb1.y;
    r1v.z = a6 * d + bb1.z;  r1v.w = a7 * d + bb1.w;
    float4* o4 = (float4*)out;
    o4[(size_t)c * 16 + sl * 2]     = r0v;
    o4[(size_t)c * 16 + sl * 2 + 1] = r1v;
}

// ---------------- launch ----------------
extern "C" void kernel_launch(void* const* d_in, const int* in_sizes, int n_in,
                              void* d_out, int out_size)
{
    const float* x      = (const float*)d_in[0];
    const int*   ei_raw = (const int*)d_in[1];
    const float* W1 = (const float*)d_in[2];
    const float* b1 = (const float*)d_in[3];
    const float* W2 = (const float*)d_in[4];
    const float* b2 = (const float*)d_in[5];
    const float* W3 = (const float*)d_in[6];
    const float* b3 = (const float*)d_in[7];
    float* out = (float*)d_out;

    constexpr int SMEM128 = (128 + 128) * LDK * 2;   // 69,632 B
    constexpr int SMEM64  = (128 + 64)  * LDK * 2;   // 52,224 B

    static cudaStream_t s2 = nullptr;
    static cudaEvent_t  eA = nullptr, eB = nullptr;
    if (s2 == nullptr) {
        cudaStreamCreateWithFlags(&s2, cudaStreamNonBlocking);
        cudaEventCreateWithFlags(&eA, cudaEventDisableTiming);
        cudaEventCreateWithFlags(&eB, cudaEventDisableTiming);
        cudaFuncSetAttribute(gemm_tc_kernel<128, 0, 1, 0>,
                             cudaFuncAttributeMaxDynamicSharedMemorySize, SMEM128);
        cudaFuncSetAttribute(gemm_tc_kernel<128, 1, 2, 1>,
                             cudaFuncAttributeMaxDynamicSharedMemorySize, SMEM128);
        cudaFuncSetAttribute(gemm_tc_kernel<64, 1, 3, 1>,
                             cudaFuncAttributeMaxDynamicSharedMemorySize, SMEM64);
    }

    const int gemmRows = (N_NODES + 127) / 128;               // 391
    const int agg128Grid = (N_NODES * 16 + 255) / 256;
    const int agg64Grid  = (N_NODES * 8 + 255) / 256;

    // fork at t=0: wt1 + gemm1 (no dinv) on s2, fully parallel with CSR build
    cudaEventRecord(eA, 0);
    cudaStreamWaitEvent(s2, eA, 0);
    wt_kernel<1, 128><<<64, 256, 0, s2>>>(W1);
    gemm_tc_kernel<128, 0, 1, 0><<<dim3(1, gemmRows), 256, SMEM128, s2>>>(x);

    // main stream: dtype + degrees + dinv + CSR + other weight transposes
    detect_zero_kernel<<<NB, 256>>>(ei_raw);
    count_kernel<<<(N_EDGES + 255) / 256, 256>>>(ei_raw);
    dinv_kernel<<<NB, 256>>>();
    scanA_kernel<<<NB, 256>>>();
    scanBC_kernel<<<NB, 256>>>();
    fill_kernel<<<(N_EDGES + 255) / 256, 256>>>(ei_raw);
    wt_kernel<2, 128><<<64, 256>>>(W2);
    wt_kernel<3, 64><<<32, 256>>>(W3);

    cudaEventRecord(eB, s2);
    cudaStreamWaitEvent(0, eB, 0);

    // apply dinv row scaling to layer-1 GEMM output, then aggregate
    scale_h_kernel<<<(N_NODES * 16 + 255) / 256, 256>>>();
    agg128_kernel<true><<<agg128Grid, 256>>>(b1);

    // ---- layer 2 ----
    gemm_tc_kernel<128, 1, 2, 1><<<dim3(1, gemmRows), 256, SMEM128>>>(nullptr);
    agg128_kernel<true><<<agg128Grid, 256>>>(b2);

    // ---- layer 3 (dim 64 -> d_out) ----
    gemm_tc_kernel<64, 1, 3, 1><<<dim3(1, gemmRows), 256, SMEM64>>>(nullptr);
    agg64_kernel<<<agg64Grid, 256>>>(out, b3);
}